// round 8
// baseline (speedup 1.0000x reference)
#include <cuda_runtime.h>
#include <cuda_bf16.h>
#include <cstdint>

#define C 80
#define KB 32                  // items per CTA tile
#define PITCH 88               // halves per item row (80 + 8 pad), conflict-free ldmatrix
#define NWARPS 5
#define NTHREADS 160
#define GRID 888               // 6 CTAs per SM x 148
#define LPT 4                  // float4 loads per thread per tile (32*80/4/160)

__device__ float g_cooc[C * C];
__device__ unsigned int g_count;

__global__ __launch_bounds__(NTHREADS, 6)
void fused_kernel(const float* __restrict__ label,
                  const float* __restrict__ pre_adj,
                  float* __restrict__ out, int batch) {
    __shared__ __nv_bfloat16 sT[2][KB * PITCH];   // double-buffered [item][class] bf16
    __shared__ float red[NWARPS];
    __shared__ int s_last;

    const int tid  = threadIdx.x;
    const int warp = tid >> 5;     // 0..4 : row-block w
    const int lane = tid & 31;
    const int g    = lane >> 2;
    const int t    = lane & 3;
    const int gi   = lane >> 3;    // ldmatrix group 0..3
    const int li   = lane & 7;

    uint32_t smem_u32;
    { uint64_t tmp; asm("cvta.to.shared.u64 %0, %1;" : "=l"(tmp) : "l"((void*)&sT[0][0]));
      smem_u32 = (uint32_t)tmp; }

    // trans-ldmatrix geometry (proven R2-R7)
    const int a_cls    = warp * 16 + ((gi & 1) ? 8 : 0);
    const int a_kbase  = ((gi & 2) ? 8 : 0) + li;
    const int b_clsadd = (gi & 2) ? 8 : 0;
    const int b_kbase  = ((gi & 1) ? 8 : 0) + li;

    // symmetric block-pair decomposition: row-block w vs col-blocks {w, w+1, w+2} mod 5
    const int bj0 = warp;
    const int bj1 = (warp + 1) % 5;
    const int bj2 = (warp + 2) % 5;

    float d[3][2][4];
    #pragma unroll
    for (int b = 0; b < 3; b++)
        #pragma unroll
        for (int n = 0; n < 2; n++)
            #pragma unroll
            for (int q = 0; q < 4; q++) d[b][n][q] = 0.0f;

    // fill coordinates: 640 float4 over 160 threads -> 4 each
    const int st_item = tid / (C / 4);            // 0..7 (base item; +8 per p)
    const int st_c4   = (tid % (C / 4)) * 4;

    const int numTiles = (batch + KB - 1) / KB;

    float4 st[LPT];
    int tile = blockIdx.x;
    if (tile < numTiles) {
        const float* p0 = label + (long long)tile * KB * C + (long long)st_item * C + st_c4;
        #pragma unroll
        for (int p = 0; p < LPT; p++)
            st[p] = *(const float4*)(p0 + (long long)p * 8 * C);
    }

    int pb = 0;
    while (tile < numTiles) {
        // ---- store staged regs as bf16 (exact truncation for {0,1}) ----
        __nv_bfloat16* buf = &sT[pb][0];
        #pragma unroll
        for (int p = 0; p < LPT; p++) {
            uint32_t lo, hi;
            asm("prmt.b32 %0, %1, %2, 0x7632;" : "=r"(lo)
                : "r"(__float_as_uint(st[p].x)), "r"(__float_as_uint(st[p].y)));
            asm("prmt.b32 %0, %1, %2, 0x7632;" : "=r"(hi)
                : "r"(__float_as_uint(st[p].z)), "r"(__float_as_uint(st[p].w)));
            *(uint2*)&buf[(st_item + p * 8) * PITCH + st_c4] = make_uint2(lo, hi);
        }

        // ---- issue next tile's loads (1-ahead; staging regs just freed) ----
        const int nxt = tile + GRID;
        if (nxt < numTiles) {
            const float* p0 = label + (long long)nxt * KB * C + (long long)st_item * C + st_c4;
            #pragma unroll
            for (int p = 0; p < LPT; p++)
                st[p] = *(const float4*)(p0 + (long long)p * 8 * C);
        }
        __syncthreads();   // buf[pb] ready; also proves all warps done MMA on buf[pb^1]

        // ---- MMA phase: row-block w vs col-blocks {bj0,bj1,bj2} ----
        const uint32_t sbase = smem_u32 + (uint32_t)(pb * KB * PITCH * 2);
        #pragma unroll
        for (int ks = 0; ks < KB / 16; ks++) {
            const int k0 = ks * 16;

            uint32_t a0, a1, a2, a3;
            {
                uint32_t addr = sbase + (uint32_t)(((k0 + a_kbase) * PITCH + a_cls) * 2);
                asm volatile("ldmatrix.sync.aligned.m8n8.x4.trans.shared.b16 "
                             "{%0,%1,%2,%3}, [%4];"
                             : "=r"(a0), "=r"(a1), "=r"(a2), "=r"(a3) : "r"(addr));
            }

            const int bjs[3] = {bj0, bj1, bj2};
            #pragma unroll
            for (int b = 0; b < 3; b++) {
                const int n0 = bjs[b] * 16;
                uint32_t b0, b1, b2, b3;
                uint32_t addr = sbase + (uint32_t)(((k0 + b_kbase) * PITCH + n0 + b_clsadd) * 2);
                asm volatile("ldmatrix.sync.aligned.m8n8.x4.trans.shared.b16 "
                             "{%0,%1,%2,%3}, [%4];"
                             : "=r"(b0), "=r"(b1), "=r"(b2), "=r"(b3) : "r"(addr));
                asm volatile(
                    "mma.sync.aligned.m16n8k16.row.col.f32.bf16.bf16.f32 "
                    "{%0,%1,%2,%3}, {%4,%5,%6,%7}, {%8,%9}, {%0,%1,%2,%3};\n"
                    : "+f"(d[b][0][0]), "+f"(d[b][0][1]), "+f"(d[b][0][2]), "+f"(d[b][0][3])
                    : "r"(a0), "r"(a1), "r"(a2), "r"(a3), "r"(b0), "r"(b1));
                asm volatile(
                    "mma.sync.aligned.m16n8k16.row.col.f32.bf16.bf16.f32 "
                    "{%0,%1,%2,%3}, {%4,%5,%6,%7}, {%8,%9}, {%0,%1,%2,%3};\n"
                    : "+f"(d[b][1][0]), "+f"(d[b][1][1]), "+f"(d[b][1][2]), "+f"(d[b][1][3])
                    : "r"(a0), "r"(a1), "r"(a2), "r"(a3), "r"(b2), "r"(b3));
            }
        }
        tile = nxt;
        pb ^= 1;
    }

    // ---- flush partials (integer-valued f32 -> exact, order-independent) ----
    {
        const int bjs[3] = {bj0, bj1, bj2};
        #pragma unroll
        for (int b = 0; b < 3; b++) {
            const int row = warp * 16 + g;
            #pragma unroll
            for (int n = 0; n < 2; n++) {
                const int col = bjs[b] * 16 + n * 8 + 2 * t;
                atomicAdd(&g_cooc[(row)     * C + col],     d[b][n][0]);
                atomicAdd(&g_cooc[(row)     * C + col + 1], d[b][n][1]);
                atomicAdd(&g_cooc[(row + 8) * C + col],     d[b][n][2]);
                atomicAdd(&g_cooc[(row + 8) * C + col + 1], d[b][n][3]);
            }
        }
    }

    // ---- last-CTA finalize ----
    __threadfence();
    __syncthreads();
    if (tid == 0)
        s_last = (atomicAdd(&g_count, 1u) == (unsigned)gridDim.x - 1u) ? 1 : 0;
    __syncthreads();
    if (!s_last) return;

    float sum = 0.0f;
    for (int idx = tid; idx < C * C; idx += NTHREADS) {
        int i = idx / C, j = idx - i * C;
        int bi = i >> 4, bj = j >> 4;
        int dd = bj - bi; if (dd < 0) dd += 5;
        float cooc = (dd <= 2) ? g_cooc[i * C + j] : g_cooc[j * C + i];  // symmetry mirror
        float cnt  = g_cooc[i * C + i];
        float adj  = (i == j) ? 1.0f : __fdividef(cooc, cnt + 1e-7f);
        float r = fabsf(pre_adj[idx] - adj);
        sum += (r < 1.0f) ? (r * r) : (r - 0.5f);
    }
    #pragma unroll
    for (int o = 16; o > 0; o >>= 1) sum += __shfl_down_sync(0xffffffffu, sum, o);
    if (lane == 0) red[warp] = sum;
    __syncthreads();
    if (warp == 0) {
        float v = (lane < NWARPS) ? red[lane] : 0.0f;
        #pragma unroll
        for (int o = 16; o > 0; o >>= 1) v += __shfl_down_sync(0xffffffffu, v, o);
        if (lane == 0) out[0] = v / (float)(C * C);
    }
    __syncthreads();   // all g_cooc reads complete before re-zero
    for (int idx = tid; idx < C * C; idx += NTHREADS) g_cooc[idx] = 0.0f;
    if (tid == 0) g_count = 0u;
}

extern "C" void kernel_launch(void* const* d_in, const int* in_sizes, int n_in,
                              void* d_out, int out_size) {
    const float* pre_adj = (const float*)d_in[0];
    const float* label   = (const float*)d_in[1];
    const int batch = in_sizes[1] / C;

    fused_kernel<<<GRID, NTHREADS>>>(label, pre_adj, (float*)d_out, batch);
}